// round 15
// baseline (speedup 1.0000x reference)
#include <cuda_runtime.h>
#include <math.h>

// SSMLayerFFTComplex: diagonal complex SSM (conjugate pairs) via exact linear
// recurrence instead of FFT convolution.
//
//   lam = -softplus(raw_lambda) + i*raw_omega          (per pair p)
//   A_d = exp(lam), factor = (A_d-1)/lam  (ZOH, DT=1)
//   w[b,p,t] = sum_i B_c[i,p] * u[b,i,t]               (real)
//   x[t]     = A_d * x[t-1] + factor * w[t]            (complex scan)
//   y[b,o,t] = sum_p C[p,o] * 2*Re(x[b,p,t])           (real GEMM)
//
// R14 post-mortem: fusion gave 0; the invariant wall is 65K threads -> 13.8
// warps/SM -> IPC ~1. R15: 256-thread blocks at FIXED work = 131K threads,
// ~28 warps/SM (43% occ):
//   K1: thread tile 8p x 4t (was 8p x 8t), same total FFMA2 (+5% loads).
//   K2: scan on threads 0-127 (unchanged); stage C SPLIT-K: half threads do
//       pp[0,64), half pp[64,128), same 8ch x 2t tile (C traffic per output
//       unchanged), partials merged via 8KB smem (+~4% instr).
// launch_bounds(256,4) -> 64 regs; prefetch dropped (occupancy hides latency).

namespace {
constexpr int T_TOT  = 4096;
constexpr int IN_CH  = 32;
constexpr int OUT_CH = 32;
constexpr int NP     = 128;
constexpr int WARM   = 32;

constexpr int K1_CHUNK = 64;
constexpr int K1_U2_BYTES = IN_CH * K1_CHUNK * 8;     // dup u64: 16,384 B
constexpr int K1_BC_FL    = IN_CH * NP;               // 4096 floats
constexpr int SMEM1_BYTES = K1_U2_BYTES + K1_BC_FL * 4;   // 32,768 B

constexpr int CHUNK  = 64;
constexpr int LW     = CHUNK + WARM;   // 96
constexpr int GST    = 66;             // g row stride (b64-aligned)
constexpr int G_BYTES    = NP * GST * 4;              // 33,792 B
constexpr int PART_BYTES = 128 * 8 * 8;               // 8,192 B (128 thr x 8 u64)
constexpr int SMEM2_BYTES = G_BYTES + PART_BYTES;     // 41,984 B

constexpr int MAXB = 8;
}

__device__ float w_buf[MAXB * T_TOT * NP];   // scratch: w[b][t][p]

typedef unsigned long long u64;

__device__ __forceinline__ u64 ffma2(u64 a, u64 b, u64 c) {
    u64 d;
    asm("fma.rn.f32x2 %0, %1, %2, %3;" : "=l"(d) : "l"(a), "l"(b), "l"(c));
    return d;
}
__device__ __forceinline__ u64 add2(u64 a, u64 b) {
    u64 d;
    asm("add.rn.f32x2 %0, %1, %2;" : "=l"(d) : "l"(a), "l"(b));
    return d;
}
__device__ __forceinline__ u64 pack2(float lo, float hi) {
    u64 d;
    asm("mov.b64 %0, {%1, %2};" : "=l"(d) : "f"(lo), "f"(hi));
    return d;
}
__device__ __forceinline__ void unpack2(u64 v, float& lo, float& hi) {
    asm("mov.b64 {%0, %1}, %2;" : "=f"(lo), "=f"(hi) : "l"(v));
}

// ---------------------------------------------------------------------------
// Kernel 1: w[b][t][p] = sum_i Bc[i][p] * u[b][i][t]   (256 thr, 8p x 4t tile)
// ---------------------------------------------------------------------------
__global__ __launch_bounds__(256, 4)
void ssm_wmix_kernel(const float* __restrict__ u,
                     const float* __restrict__ Bc)
{
    extern __shared__ char smem1[];
    u64*   u_s2 = reinterpret_cast<u64*>(smem1);               // [IN_CH][64] dup pairs
    float* bc_s = reinterpret_cast<float*>(smem1 + K1_U2_BYTES); // [IN_CH][NP]

    const int tid = threadIdx.x;
    const int ct  = blockIdx.x;
    const int b   = blockIdx.y;
    const int t0  = ct * K1_CHUNK;

    const float* ug = u + (size_t)b * IN_CH * T_TOT + t0;
    for (int idx = tid; idx < IN_CH * K1_CHUNK; idx += 256) {
        int i = idx >> 6;
        int j = idx & 63;
        float v = ug[i * T_TOT + j];
        u_s2[idx] = pack2(v, v);          // duplicated pair
    }
    for (int idx = tid; idx < K1_BC_FL; idx += 256) bc_s[idx] = Bc[idx];
    __syncthreads();

    const int pq = tid & 15;              // p block: [8*pq, 8*pq+8)
    const int tq = tid >> 4;              // t block: [4*tq, 4*tq+4)  (16 blocks)

    u64 acc[4][4];                        // [t][p-pair]
#pragma unroll
    for (int t = 0; t < 4; ++t)
#pragma unroll
        for (int q = 0; q < 4; ++q) acc[t][q] = 0ull;

    const float* bcb = bc_s + 8 * pq;
    const u64*   ub2 = u_s2 + 4 * tq;
#pragma unroll 4
    for (int k = 0; k < IN_CH; ++k) {
        ulonglong2 t01 = *reinterpret_cast<const ulonglong2*>(ub2 + (size_t)k * K1_CHUNK + 0);
        ulonglong2 t23 = *reinterpret_cast<const ulonglong2*>(ub2 + (size_t)k * K1_CHUNK + 2);
        ulonglong2 bcp = *reinterpret_cast<const ulonglong2*>(bcb + k * NP);
        ulonglong2 bcq = *reinterpret_cast<const ulonglong2*>(bcb + k * NP + 4);
        u64 td[4] = {t01.x, t01.y, t23.x, t23.y};
        u64 bp[4] = {bcp.x, bcp.y, bcq.x, bcq.y};
#pragma unroll
        for (int t = 0; t < 4; ++t)
#pragma unroll
            for (int q = 0; q < 4; ++q)
                acc[t][q] = ffma2(bp[q], td[t], acc[t][q]);
    }

    float* wb = w_buf + ((size_t)b * T_TOT + t0 + 4 * tq) * NP + 8 * pq;
#pragma unroll
    for (int t = 0; t < 4; ++t) {
        ulonglong2 v0; v0.x = acc[t][0]; v0.y = acc[t][1];
        ulonglong2 v1; v1.x = acc[t][2]; v1.y = acc[t][3];
        *reinterpret_cast<ulonglong2*>(wb + t * NP)     = v0;
        *reinterpret_cast<ulonglong2*>(wb + t * NP + 4) = v1;
    }
}

// ---------------------------------------------------------------------------
// Kernel 2: scan (threads 0-127) + split-K output GEMM (all 256)
// ---------------------------------------------------------------------------
__global__ __launch_bounds__(256, 4)
void ssm_scan_kernel(const float* __restrict__ raw_lambda,
                     const float* __restrict__ raw_omega,
                     const float* __restrict__ Cp,   // [NP][OUT_CH]
                     float* __restrict__ y)          // [B][OUT_CH][T]
{
    extern __shared__ char smem_raw[];
    float* g_s  = reinterpret_cast<float*>(smem_raw);            // [NP][GST]
    u64*   part = reinterpret_cast<u64*>(smem_raw + G_BYTES);    // [128][8]

    const int tid   = threadIdx.x;
    const int chunk = blockIdx.x;
    const int b     = blockIdx.y;
    const int t0    = chunk * CHUNK;

    // ---- stage B: scan on threads 0-127 (thread = pair p) ----
    if (tid < NP) {
        const int p = tid;
        float rl = raw_lambda[p];
        float li = raw_omega[p];
        float lr = -log1pf(expf(rl));        // -softplus
        float er = expf(lr);
        float ar = er * cosf(li);            // A_d
        float ai = er * sinf(li);
        float nr = ar - 1.0f, ni = ai;
        float den = lr * lr + li * li;
        float fr, fi;
        if (den > 1e-12f) {
            float inv = 1.0f / den;
            fr = (nr * lr + ni * li) * inv;  // (A_d-1)/lam
            fi = (ni * lr - nr * li) * inv;
        } else {
            fr = 1.0f; fi = 0.0f;            // DT = 1
        }
        fr *= 2.0f; fi *= 2.0f;              // fold 2*Re(conjugate pair)

        const float* wrow = w_buf + (size_t)b * T_TOT * NP + p;
        float xr = 0.0f, xi = 0.0f;
#pragma unroll 1
        for (int jb = 0; jb < LW; jb += 8) {
            const int tb = t0 - WARM + jb;
            float wv[8];
            if (tb >= 0) {                   // uniform per block (WARM%8==0)
#pragma unroll
                for (int k = 0; k < 8; ++k) wv[k] = wrow[(size_t)(tb + k) * NP];
            } else {
#pragma unroll
                for (int k = 0; k < 8; ++k) wv[k] = 0.0f;
            }
            float xrs[8];
#pragma unroll
            for (int k = 0; k < 8; ++k) {
                float nxr = fmaf(ar, xr, fmaf(-ai, xi, fr * wv[k]));
                float nxi = fmaf(ar, xi, fmaf( ai, xr, fi * wv[k]));
                xr = nxr; xi = nxi;
                xrs[k] = xr;                 // already x2 via factor
            }
            if (jb >= WARM) {
                float* gr = &g_s[p * GST + (jb - WARM)];
                *reinterpret_cast<u64*>(gr + 0) = pack2(xrs[0], xrs[1]);
                *reinterpret_cast<u64*>(gr + 2) = pack2(xrs[2], xrs[3]);
                *reinterpret_cast<u64*>(gr + 4) = pack2(xrs[4], xrs[5]);
                *reinterpret_cast<u64*>(gr + 6) = pack2(xrs[6], xrs[7]);
            }
        }
    }

    __syncthreads();

    // ---- stage C (split-K): y[o,t] = sum_p C[p,o] * g[p,t] ----
    // thread = (kh half of pp) x (8ch x 2t); same C-traffic per output as R13.
    const int kh   = tid >> 7;                      // pp half 0/1
    const int t128 = tid & 127;
    const int wp2  = t128 >> 5;
    const int lane = tid & 31;
    const int oct  = lane & 3;                      // channel octet
    const int tl   = wp2 * 16 + (lane >> 2) * 2;    // local t (even), 0..62

    u64 a01t0 = 0ull, a23t0 = 0ull, a45t0 = 0ull, a67t0 = 0ull;
    u64 a01t1 = 0ull, a23t1 = 0ull, a45t1 = 0ull, a67t1 = 0ull;

    const float* cb = Cp + oct * 8;
    const int pp0 = kh * 64;
#pragma unroll 8
    for (int pp = pp0; pp < pp0 + 64; ++pp) {
        ulonglong2 cA = *reinterpret_cast<const ulonglong2*>(cb + pp * OUT_CH);
        ulonglong2 cB = *reinterpret_cast<const ulonglong2*>(cb + pp * OUT_CH + 4);
        u64 gp = *reinterpret_cast<const u64*>(&g_s[pp * GST + tl]);
        float g0, g1;
        unpack2(gp, g0, g1);
        u64 gg0 = pack2(g0, g0);
        u64 gg1 = pack2(g1, g1);
        a01t0 = ffma2(cA.x, gg0, a01t0);
        a23t0 = ffma2(cA.y, gg0, a23t0);
        a45t0 = ffma2(cB.x, gg0, a45t0);
        a67t0 = ffma2(cB.y, gg0, a67t0);
        a01t1 = ffma2(cA.x, gg1, a01t1);
        a23t1 = ffma2(cA.y, gg1, a23t1);
        a45t1 = ffma2(cB.x, gg1, a45t1);
        a67t1 = ffma2(cB.y, gg1, a67t1);
    }

    // ---- merge halves: half 1 publishes partials, half 0 adds + stores ----
    if (kh) {
        u64* pb = part + t128 * 8;
        pb[0] = a01t0; pb[1] = a23t0; pb[2] = a45t0; pb[3] = a67t0;
        pb[4] = a01t1; pb[5] = a23t1; pb[6] = a45t1; pb[7] = a67t1;
    }
    __syncthreads();
    if (!kh) {
        const u64* pb = part + t128 * 8;
        a01t0 = add2(a01t0, pb[0]);
        a23t0 = add2(a23t0, pb[1]);
        a45t0 = add2(a45t0, pb[2]);
        a67t0 = add2(a67t0, pb[3]);
        a01t1 = add2(a01t1, pb[4]);
        a23t1 = add2(a23t1, pb[5]);
        a45t1 = add2(a45t1, pb[6]);
        a67t1 = add2(a67t1, pb[7]);

        const int tg = t0 + tl;
        float* yb = y + ((size_t)b * OUT_CH + oct * 8) * T_TOT + tg;
        float c0t0, c1t0, c0t1, c1t1;
        unpack2(a01t0, c0t0, c1t0); unpack2(a01t1, c0t1, c1t1);
        *reinterpret_cast<float2*>(yb + 0 * T_TOT) = make_float2(c0t0, c0t1);
        *reinterpret_cast<float2*>(yb + 1 * T_TOT) = make_float2(c1t0, c1t1);
        unpack2(a23t0, c0t0, c1t0); unpack2(a23t1, c0t1, c1t1);
        *reinterpret_cast<float2*>(yb + 2 * T_TOT) = make_float2(c0t0, c0t1);
        *reinterpret_cast<float2*>(yb + 3 * T_TOT) = make_float2(c1t0, c1t1);
        unpack2(a45t0, c0t0, c1t0); unpack2(a45t1, c0t1, c1t1);
        *reinterpret_cast<float2*>(yb + 4 * T_TOT) = make_float2(c0t0, c0t1);
        *reinterpret_cast<float2*>(yb + 5 * T_TOT) = make_float2(c1t0, c1t1);
        unpack2(a67t0, c0t0, c1t0); unpack2(a67t1, c0t1, c1t1);
        *reinterpret_cast<float2*>(yb + 6 * T_TOT) = make_float2(c0t0, c0t1);
        *reinterpret_cast<float2*>(yb + 7 * T_TOT) = make_float2(c1t0, c1t1);
    }
}

extern "C" void kernel_launch(void* const* d_in, const int* in_sizes, int n_in,
                              void* d_out, int out_size)
{
    const float* u   = (const float*)d_in[0];
    const float* rlb = (const float*)d_in[1];
    const float* rom = (const float*)d_in[2];
    const float* Bc  = (const float*)d_in[3];
    const float* Cp  = (const float*)d_in[4];
    float* y = (float*)d_out;

    const int B = in_sizes[0] / (IN_CH * T_TOT);  // 8

    cudaFuncSetAttribute(ssm_wmix_kernel,
                         cudaFuncAttributeMaxDynamicSharedMemorySize, SMEM1_BYTES);
    cudaFuncSetAttribute(ssm_scan_kernel,
                         cudaFuncAttributeMaxDynamicSharedMemorySize, SMEM2_BYTES);

    dim3 grid(T_TOT / CHUNK, B);   // 64 x 8 = 512 blocks each, 256 thr/block
    ssm_wmix_kernel<<<grid, 256, SMEM1_BYTES>>>(u, Bc);
    ssm_scan_kernel<<<grid, 256, SMEM2_BYTES>>>(rlb, rom, Cp, y);
}

// round 16
// speedup vs baseline: 1.1731x; 1.1731x over previous
#include <cuda_runtime.h>
#include <math.h>

// SSMLayerFFTComplex: diagonal complex SSM (conjugate pairs) via exact linear
// recurrence instead of FFT convolution.
//
//   lam = -softplus(raw_lambda) + i*raw_omega          (per pair p)
//   A_d = exp(lam), factor = (A_d-1)/lam  (ZOH, DT=1)
//   w[b,p,t] = sum_i B_c[i,p] * u[b,i,t]               (real)
//   x[t]     = A_d * x[t-1] + factor * w[t]            (complex scan)
//   y[b,o,t] = sum_p C[p,o] * 2*Re(x[b,p,t])           (real GEMM)
//
// R15 finding: issue% invariant (~30%) across 14->28 warps/SM -> LSU op
// dispatch (4cyc/LDG floor) is the wall; stage C's C-loads duplicated per
// 2-t slot are its biggest term. R16: K2 CHUNK=128 (WARM=32 -> redundancy
// 1.25), stage-C thread tile 8ch x 4t: per pair 2 LDG.128 + 1 LDS.128 feed
// 16 FFMA2 -> stage-C LSU cycles/SM drop ~4x. float4 y stores. K1 verbatim
// R13 (best measured).

namespace {
constexpr int T_TOT  = 4096;
constexpr int IN_CH  = 32;
constexpr int OUT_CH = 32;
constexpr int NP     = 128;
constexpr int WARM   = 32;

constexpr int K1_CHUNK = 64;
constexpr int K1_U2_BYTES = IN_CH * K1_CHUNK * 8;     // dup u64: 16,384 B
constexpr int K1_BC_FL    = IN_CH * NP;               // 4096 floats
constexpr int SMEM1_BYTES = K1_U2_BYTES + K1_BC_FL * 4;   // 32,768 B

constexpr int CHUNK  = 128;            // K2 useful timesteps per block
constexpr int LW     = CHUNK + WARM;   // 160
constexpr int GST    = 132;            // g row stride: mult of 4 (LDS.128-aligned)
constexpr int G_FL   = NP * GST;       // 16,896 floats
constexpr int SMEM2_BYTES = G_FL * (int)sizeof(float);  // 67,584 B

constexpr int MAXB = 8;
}

__device__ float w_buf[MAXB * T_TOT * NP];   // scratch: w[b][t][p]

typedef unsigned long long u64;

__device__ __forceinline__ u64 ffma2(u64 a, u64 b, u64 c) {
    u64 d;
    asm("fma.rn.f32x2 %0, %1, %2, %3;" : "=l"(d) : "l"(a), "l"(b), "l"(c));
    return d;
}
__device__ __forceinline__ u64 pack2(float lo, float hi) {
    u64 d;
    asm("mov.b64 %0, {%1, %2};" : "=l"(d) : "f"(lo), "f"(hi));
    return d;
}
__device__ __forceinline__ void unpack2(u64 v, float& lo, float& hi) {
    asm("mov.b64 {%0, %1}, %2;" : "=f"(lo), "=f"(hi) : "l"(v));
}

// ---------------------------------------------------------------------------
// Kernel 1: w[b][t][p] = sum_i Bc[i][p] * u[b][i][t]   (verbatim R13: 128 thr,
// 8p x 8t tile, u staged pre-duplicated as (v,v) u64 -> pack-free loop)
// ---------------------------------------------------------------------------
__global__ __launch_bounds__(128, 4)
void ssm_wmix_kernel(const float* __restrict__ u,
                     const float* __restrict__ Bc)
{
    extern __shared__ char smem1[];
    u64*   u_s2 = reinterpret_cast<u64*>(smem1);                  // [IN_CH][64]
    float* bc_s = reinterpret_cast<float*>(smem1 + K1_U2_BYTES);  // [IN_CH][NP]

    const int tid = threadIdx.x;
    const int ct  = blockIdx.x;
    const int b   = blockIdx.y;
    const int t0  = ct * K1_CHUNK;

    const float* ug = u + (size_t)b * IN_CH * T_TOT + t0;
    for (int idx = tid; idx < IN_CH * K1_CHUNK; idx += 128) {
        int i = idx >> 6;
        int j = idx & 63;
        float v = ug[i * T_TOT + j];
        u_s2[idx] = pack2(v, v);          // duplicated pair
    }
    for (int idx = tid; idx < K1_BC_FL; idx += 128) bc_s[idx] = Bc[idx];
    __syncthreads();

    const int pq = tid & 15;              // p block: [8*pq, 8*pq+8)
    const int tq = tid >> 4;              // t block: [8*tq, 8*tq+8)

    u64 acc[8][4];
#pragma unroll
    for (int t = 0; t < 8; ++t)
#pragma unroll
        for (int q = 0; q < 4; ++q) acc[t][q] = 0ull;

    const float* bcb = bc_s + 8 * pq;
    const u64*   ub2 = u_s2 + 8 * tq;
#pragma unroll 4
    for (int k = 0; k < IN_CH; ++k) {
        ulonglong2 t01 = *reinterpret_cast<const ulonglong2*>(ub2 + (size_t)k * K1_CHUNK + 0);
        ulonglong2 t23 = *reinterpret_cast<const ulonglong2*>(ub2 + (size_t)k * K1_CHUNK + 2);
        ulonglong2 t45 = *reinterpret_cast<const ulonglong2*>(ub2 + (size_t)k * K1_CHUNK + 4);
        ulonglong2 t67 = *reinterpret_cast<const ulonglong2*>(ub2 + (size_t)k * K1_CHUNK + 6);
        ulonglong2 bcp = *reinterpret_cast<const ulonglong2*>(bcb + k * NP);
        ulonglong2 bcq = *reinterpret_cast<const ulonglong2*>(bcb + k * NP + 4);
        u64 td[8] = {t01.x, t01.y, t23.x, t23.y, t45.x, t45.y, t67.x, t67.y};
        u64 bp[4] = {bcp.x, bcp.y, bcq.x, bcq.y};
#pragma unroll
        for (int t = 0; t < 8; ++t)
#pragma unroll
            for (int q = 0; q < 4; ++q)
                acc[t][q] = ffma2(bp[q], td[t], acc[t][q]);
    }

    float* wb = w_buf + ((size_t)b * T_TOT + t0 + 8 * tq) * NP + 8 * pq;
#pragma unroll
    for (int t = 0; t < 8; ++t) {
        ulonglong2 v0; v0.x = acc[t][0]; v0.y = acc[t][1];
        ulonglong2 v1; v1.x = acc[t][2]; v1.y = acc[t][3];
        *reinterpret_cast<ulonglong2*>(wb + t * NP)     = v0;
        *reinterpret_cast<ulonglong2*>(wb + t * NP + 4) = v1;
    }
}

// ---------------------------------------------------------------------------
// Kernel 2: scan (CHUNK=128) + output GEMM with 8ch x 4t thread tile
// ---------------------------------------------------------------------------
__global__ __launch_bounds__(128, 3)
void ssm_scan_kernel(const float* __restrict__ raw_lambda,
                     const float* __restrict__ raw_omega,
                     const float* __restrict__ Cp,   // [NP][OUT_CH]
                     float* __restrict__ y)          // [B][OUT_CH][T]
{
    extern __shared__ float smem[];
    float* g_s = smem;              // [NP][GST]  (full 128-t chunk)

    const int tid   = threadIdx.x;
    const int wp    = tid >> 5;
    const int lane  = tid & 31;
    const int chunk = blockIdx.x;
    const int b     = blockIdx.y;
    const int t0    = chunk * CHUNK;

    // ---- per-pair parameters (thread = pair p) ----
    const int p = tid;
    float rl = raw_lambda[p];
    float li = raw_omega[p];
    float lr = -log1pf(expf(rl));            // -softplus
    float er = expf(lr);
    float ar = er * cosf(li);                // A_d
    float ai = er * sinf(li);
    float nr = ar - 1.0f, ni = ai;
    float den = lr * lr + li * li;
    float fr, fi;
    if (den > 1e-12f) {
        float inv = 1.0f / den;
        fr = (nr * lr + ni * li) * inv;      // (A_d-1)/lam
        fi = (ni * lr - nr * li) * inv;
    } else {
        fr = 1.0f; fi = 0.0f;                // DT = 1
    }
    fr *= 2.0f; fi *= 2.0f;                  // fold 2*Re(conjugate pair)

    // ---- stage B: scan over [t0-WARM, t0+CHUNK) with group prefetch ----
    const float* wrow = w_buf + (size_t)b * T_TOT * NP + p;
    float xr = 0.0f, xi = 0.0f;
    float wa[8], wb8[8];

#define LOADGRP(JB, DST)                                              \
    {   const int tb_ = t0 - WARM + (JB);                             \
        if (tb_ >= 0) {                                               \
            _Pragma("unroll")                                         \
            for (int k_ = 0; k_ < 8; ++k_)                            \
                (DST)[k_] = wrow[(size_t)(tb_ + k_) * NP];            \
        } else {                                                      \
            _Pragma("unroll")                                         \
            for (int k_ = 0; k_ < 8; ++k_) (DST)[k_] = 0.0f;          \
        }                                                             \
    }

#define SCANGRP(JB, SRC)                                              \
    {   float xrs_[8];                                                \
        _Pragma("unroll")                                             \
        for (int k_ = 0; k_ < 8; ++k_) {                              \
            float nxr_ = fmaf(ar, xr, fmaf(-ai, xi, fr * (SRC)[k_])); \
            float nxi_ = fmaf(ar, xi, fmaf( ai, xr, fi * (SRC)[k_])); \
            xr = nxr_; xi = nxi_;                                     \
            xrs_[k_] = xr;                                            \
        }                                                             \
        if ((JB) >= WARM) {                                           \
            float* gr_ = &g_s[p * GST + ((JB) - WARM)];               \
            *reinterpret_cast<u64*>(gr_ + 0) = pack2(xrs_[0], xrs_[1]); \
            *reinterpret_cast<u64*>(gr_ + 2) = pack2(xrs_[2], xrs_[3]); \
            *reinterpret_cast<u64*>(gr_ + 4) = pack2(xrs_[4], xrs_[5]); \
            *reinterpret_cast<u64*>(gr_ + 6) = pack2(xrs_[6], xrs_[7]); \
        }                                                             \
    }

    LOADGRP(0, wa);
#pragma unroll 1
    for (int jb = 0; jb < LW; jb += 16) {
        LOADGRP(jb + 8, wb8);        // prefetch while wa's chain runs
        SCANGRP(jb, wa);
        if (jb + 16 < LW) LOADGRP(jb + 16, wa);
        SCANGRP(jb + 8, wb8);
    }
#undef LOADGRP
#undef SCANGRP

    __syncthreads();

    // ---- stage C: y[o, t] = sum_p C[p,o] * g[p,t], thread = 8ch x 4t ----
    // C via coalesced L1-hot LDG.128; g via one LDS.128 per pair (4 t).
    const int oct = lane & 3;                // channel octet 0..3
    const int tl  = wp * 32 + (lane >> 2) * 4;   // local t (mult of 4), 0..124

    u64 acc[4][4];                           // [t][ch-pair]
#pragma unroll
    for (int t = 0; t < 4; ++t)
#pragma unroll
        for (int q = 0; q < 4; ++q) acc[t][q] = 0ull;

    const float* cb = Cp + oct * 8;
    const float* gp = &g_s[tl];
#pragma unroll 4
    for (int pp = 0; pp < NP; ++pp) {
        ulonglong2 cA = *reinterpret_cast<const ulonglong2*>(cb + pp * OUT_CH);
        ulonglong2 cB = *reinterpret_cast<const ulonglong2*>(cb + pp * OUT_CH + 4);
        float4 g4 = *reinterpret_cast<const float4*>(gp + pp * GST);
        u64 gg[4];
        gg[0] = pack2(g4.x, g4.x);
        gg[1] = pack2(g4.y, g4.y);
        gg[2] = pack2(g4.z, g4.z);
        gg[3] = pack2(g4.w, g4.w);
#pragma unroll
        for (int t = 0; t < 4; ++t) {
            acc[t][0] = ffma2(cA.x, gg[t], acc[t][0]);
            acc[t][1] = ffma2(cA.y, gg[t], acc[t][1]);
            acc[t][2] = ffma2(cB.x, gg[t], acc[t][2]);
            acc[t][3] = ffma2(cB.y, gg[t], acc[t][3]);
        }
    }

    // ---- transpose to channel-major and store float4 per channel ----
    float o[8][4];
#pragma unroll
    for (int t = 0; t < 4; ++t) {
        unpack2(acc[t][0], o[0][t], o[1][t]);
        unpack2(acc[t][1], o[2][t], o[3][t]);
        unpack2(acc[t][2], o[4][t], o[5][t]);
        unpack2(acc[t][3], o[6][t], o[7][t]);
    }
    const int tg = t0 + tl;
    float* yb = y + ((size_t)b * OUT_CH + oct * 8) * T_TOT + tg;
#pragma unroll
    for (int ch = 0; ch < 8; ++ch)
        *reinterpret_cast<float4*>(yb + ch * T_TOT) =
            make_float4(o[ch][0], o[ch][1], o[ch][2], o[ch][3]);
}

extern "C" void kernel_launch(void* const* d_in, const int* in_sizes, int n_in,
                              void* d_out, int out_size)
{
    const float* u   = (const float*)d_in[0];
    const float* rlb = (const float*)d_in[1];
    const float* rom = (const float*)d_in[2];
    const float* Bc  = (const float*)d_in[3];
    const float* Cp  = (const float*)d_in[4];
    float* y = (float*)d_out;

    const int B = in_sizes[0] / (IN_CH * T_TOT);  // 8

    cudaFuncSetAttribute(ssm_wmix_kernel,
                         cudaFuncAttributeMaxDynamicSharedMemorySize, SMEM1_BYTES);
    cudaFuncSetAttribute(ssm_scan_kernel,
                         cudaFuncAttributeMaxDynamicSharedMemorySize, SMEM2_BYTES);

    dim3 grid1(T_TOT / K1_CHUNK, B);   // 64 x 8 = 512 blocks
    ssm_wmix_kernel<<<grid1, 128, SMEM1_BYTES>>>(u, Bc);

    dim3 grid2(T_TOT / CHUNK, B);      // 32 x 8 = 256 blocks, 3/SM capacity
    ssm_scan_kernel<<<grid2, 128, SMEM2_BYTES>>>(rlb, rom, Cp, y);
}